// round 16
// baseline (speedup 1.0000x reference)
#include <cuda_runtime.h>
#include <cuda_fp16.h>

typedef unsigned int uint;

// Problem constants (fixed by the dataset)
#define CC     16
#define NN     64
#define DQK    32
#define HIDN   64
#define MAXE   512
#define BMAX   16
#define PLANE  16384

// pixel-major fp16 tile (hi only): [324 pixels][20 uints pitch], 16 ch-pairs
#define TPITCH_U 20
#define TILE_U   (324*TPITCH_U)
#define TILE_BYTES (TILE_U*4)            // 25920

// ---------------- scratch ----------------------------------------------------
__device__ float g_Xa [BMAX*CC*PLANE];
__device__ float g_Xb [BMAX*CC*PLANE];
__device__ float g_M0 [BMAX*CC*PLANE];
__device__ float g_M1 [BMAX*CC*PLANE];
__device__ float g_AB0[BMAX*NN*128];
__device__ float g_AB1[BMAX*NN*128];
__device__ float g_T9 [CC*9];
__device__ int   g_off[NN+1];
__device__ int   g_lj [MAXE];
// fp16-split weight fragment tables: [(ks*N + n)*4 + q] -> (b0h,b1h,b0l,b1l)
__device__ uint4 g_pBM[9*16*4];
__device__ uint4 g_pBg[18*32*4];
__device__ uint4 g_pBc[18*16*4];

__device__ __forceinline__ float sigf(float x){ return 1.f/(1.f+__expf(-x)); }

// ---------------- fp16 helpers ------------------------------------------------
__device__ __forceinline__ uint packh2(__half a, __half b){
    __half2 h = __halves2half2(a, b);
    return *reinterpret_cast<uint*>(&h);
}
__device__ __forceinline__ uint pkhi(float v0, float v1){
    __half2 h = __floats2half2_rn(v0, v1);
    return *reinterpret_cast<uint*>(&h);
}
__device__ __forceinline__ float2 hirec(uint e){
    __half2 hh = *reinterpret_cast<__half2*>(&e);
    return __half22float2(hh);
}

__device__ __forceinline__ void mmah(float c[4], const uint a[4], uint b0, uint b1){
    asm volatile("mma.sync.aligned.m16n8k16.row.col.f32.f16.f16.f32 "
        "{%0,%1,%2,%3},{%4,%5,%6,%7},{%8,%9},{%0,%1,%2,%3};"
        : "+f"(c[0]),"+f"(c[1]),"+f"(c[2]),"+f"(c[3])
        : "r"(a[0]),"r"(a[1]),"r"(a[2]),"r"(a[3]),"r"(b0),"r"(b1));
}

__device__ __forceinline__ void ldsm4(uint r[4], uint addr){
    asm volatile("ldmatrix.sync.aligned.m8n8.x4.shared.b16 {%0,%1,%2,%3}, [%4];"
        : "=r"(r[0]),"=r"(r[1]),"=r"(r[2]),"=r"(r[3]) : "r"(addr));
}

// ---------------- weight prepack (runs once) ----------------------------------
__device__ __forceinline__ void prep_one(const float* __restrict__ W,
                                         uint4* __restrict__ out,
                                         int CIN, int N, int i)
{
    int q = i & 3; int t = i >> 2; int n = t % N; int ks = t / N;
    float w[4]; __half h[4], l[4];
    int kk[4] = { ks*16 + 2*q, ks*16 + 2*q + 1, ks*16 + 2*q + 8, ks*16 + 2*q + 9 };
    #pragma unroll
    for (int j = 0; j < 4; j++) {
        int k = kk[j];
        w[j] = W[n*CIN*9 + (k % CIN)*9 + (k / CIN)];
        h[j] = __float2half_rn(w[j]);
        l[j] = __float2half_rn(w[j] - __half2float(h[j]));
    }
    uint4 o;
    o.x = packh2(h[0], h[1]);
    o.y = packh2(h[2], h[3]);
    o.z = packh2(l[0], l[1]);
    o.w = packh2(l[2], l[3]);
    out[(ks*N + n)*4 + q] = o;
}

__global__ void k_prepAll(const float* __restrict__ wm,
                          const float* __restrict__ wg,
                          const float* __restrict__ wc,
                          uint4* __restrict__ outM, uint4* __restrict__ outG,
                          uint4* __restrict__ outC)
{
    int i = blockIdx.x*256 + threadIdx.x;
    if (i < 576)       prep_one(wm, outM, 16, 16, i);
    else if (i < 2880) prep_one(wg, outG, 32, 32, i - 576);
    else if (i < 4032) prep_one(wc, outC, 32, 16, i - 2880);
}

// csr build + T9 table in one launch
__global__ void k_csrT9(const int* __restrict__ eidx, int E,
                        int* __restrict__ off, int* __restrict__ lj,
                        const float* __restrict__ gw, float* __restrict__ T9)
{
    __shared__ int se[MAXE*2];
    int tid = threadIdx.x;
    for (int i = tid; i < 2*E; i += 256) se[i] = eidx[i];
    if (tid < CC*9) {
        int c = tid / 9, cls = tid - c*9, ry = cls/3, rx = cls - ry*3;
        float s = 0.f;
        #pragma unroll
        for (int ky = 0; ky < 3; ky++) {
            if ((ry == 0 && ky == 0) || (ry == 2 && ky == 2)) continue;
            #pragma unroll
            for (int kx = 0; kx < 3; kx++) {
                if ((rx == 0 && kx == 0) || (rx == 2 && kx == 2)) continue;
                s += gw[c*9 + ky*3 + kx];
            }
        }
        T9[tid] = s;
    }
    __syncthreads();
    if (tid == 0) {
        int cnt[NN];
        for (int i = 0; i < NN; i++) cnt[i] = 0;
        for (int e = 0; e < E; e++) cnt[se[2*e]]++;
        int acc = 0;
        for (int i = 0; i < NN; i++) { off[i] = acc; acc += cnt[i]; cnt[i] = 0; }
        off[NN] = acc;
        for (int e = 0; e < E; e++) {
            int i = se[2*e];
            int s = off[i] + cnt[i]++;
            lj[s] = se[2*e + 1];
        }
    }
}

// ---------------- tile loader (pixel-major, hi only) ---------------------------
__device__ __forceinline__ void load_tile_hi(uint* sTu,
        const float* __restrict__ src, int cp0,
        int b, int p16, int q16)
{
    for (int i = threadIdx.x; i < 324*8; i += 256) {
        int cp = i / 324; int pix = i - cp*324;
        int yy = pix/18, xx = pix - yy*18;
        int ly = yy - 1, lx = xx - 1;
        float v0 = 0.f, v1 = 0.f;
        if ((unsigned)ly < 16u && (unsigned)lx < 16u) {
            const float* p = &src[((b*CC + 2*cp)*128 + p16 + ly)*128 + (q16 + lx)];
            v0 = p[0]; v1 = p[PLANE];
        }
        sTu[pix*TPITCH_U + cp0 + cp] = pkhi(v0, v1);
    }
}

// ---------------- fp16 2-term conv GEMM core (ldmatrix, sw-pipelined) ----------
template<int CIN,int NT>
__device__ __forceinline__ void mma_convh(uint sbase,
                                          const uint4* __restrict__ pB,
                                          const float* s_bias,
                                          float acc[2][NT][4])
{
    constexpr int N = NT*8;
    constexpr int KSTEPS = CIN*9/16;
    int lane = threadIdx.x & 31;
    int wid  = threadIdx.x >> 5;
    int g = lane >> 2, q = lane & 3;
    int m0 = wid*2;
    int x = lane & 15, colsel = lane >> 4;

    #pragma unroll
    for (int mm = 0; mm < 2; mm++)
        #pragma unroll
        for (int nt = 0; nt < NT; nt++) {
            float b0 = s_bias[nt*8 + q*2], b1 = s_bias[nt*8 + q*2 + 1];
            acc[mm][nt][0] = b0; acc[mm][nt][1] = b1;
            acc[mm][nt][2] = b0; acc[mm][nt][3] = b1;
        }

    #pragma unroll 2
    for (int ks = 0; ks < KSTEPS; ks++) {
        int tap = (CIN == 16) ? ks : (ks >> 1);
        int sub = (CIN == 16) ? 0  : (ks & 1);
        int ty = tap/3, tx = tap - ty*3;
        uint ah[2][4];
        uint4 bv[NT];
        #pragma unroll
        for (int mm = 0; mm < 2; mm++) {
            int row = (m0 + mm + ty)*18 + x + tx;
            uint addr = sbase + (uint)((row*40 + sub*16 + colsel*8)*2);
            ldsm4(ah[mm], addr);
        }
        #pragma unroll
        for (int nt = 0; nt < NT; nt++)
            bv[nt] = pB[(ks*N + nt*8 + g)*4 + q];
        #pragma unroll
        for (int nt = 0; nt < NT; nt++) {
            #pragma unroll
            for (int mm = 0; mm < 2; mm++) {
                mmah(acc[mm][nt], ah[mm], bv[nt].x, bv[nt].y);
                mmah(acc[mm][nt], ah[mm], bv[nt].z, bv[nt].w);
            }
        }
    }
}

// ---------------- initial conv + mean/qk/AB kernel (seed only) ----------------
__global__ __launch_bounds__(256) void k_convQ(const float* __restrict__ X,
    const uint4* __restrict__ pBM, const float* __restrict__ bm,
    const float* __restrict__ wq, const float* __restrict__ bq,
    const float* __restrict__ wk, const float* __restrict__ bk,
    const float* __restrict__ W1,
    float* __restrict__ M, float* __restrict__ AB)
{
    int bn = blockIdx.x; int b = bn >> 6, n = bn & 63;
    int p16 = (n >> 3)*16, q16 = (n & 7)*16;
    extern __shared__ uint sTu[];
    __shared__ float s_bias[16];
    __shared__ float s_xm[16];
    __shared__ float s_qk[64];
    load_tile_hi(sTu, X, 0, b, p16, q16);
    if (threadIdx.x < 16) s_bias[threadIdx.x] = bm[threadIdx.x];

    int tid = threadIdx.x;
    uint sbase = (uint)__cvta_generic_to_shared(sTu);
    {
        int w = tid >> 5, lane = tid & 31;
        for (int c = w*2; c < w*2 + 2; c++) {
            float s = 0.f;
            for (int i = lane; i < 256; i += 32) {
                int y = i >> 4, x = i & 15;
                s += X[((b*CC + c)*128 + p16 + y)*128 + q16 + x];
            }
            #pragma unroll
            for (int o = 16; o; o >>= 1) s += __shfl_down_sync(0xffffffffu, s, o);
            if (!lane) s_xm[c] = s * (1.f/256.f);
        }
    }
    __syncthreads();

    float acc[2][2][4];
    mma_convh<16,2>(sbase, pBM, s_bias, acc);

    int lane = tid & 31, wid = tid >> 5;
    int g = lane >> 2, q = lane & 3, m0 = wid*2;
    #pragma unroll
    for (int mm = 0; mm < 2; mm++) {
        int y = m0 + mm;
        #pragma unroll
        for (int nt = 0; nt < 2; nt++) {
            int co = nt*8 + q*2;
            int r0 = ((b*CC + co)*128 + p16 + y)*128 + q16;
            int r1 = r0 + PLANE;
            M[r0 + g]     = acc[mm][nt][0];
            M[r1 + g]     = acc[mm][nt][1];
            M[r0 + g + 8] = acc[mm][nt][2];
            M[r1 + g + 8] = acc[mm][nt][3];
        }
    }
    __syncthreads();
    if (tid < 64) {
        int d = tid & 31;
        const float* wM = (tid < 32) ? wq : wk;
        const float* bM = (tid < 32) ? bq : bk;
        float a = bM[d];
        #pragma unroll
        for (int c = 0; c < CC; c++) a += s_xm[c]*wM[c*DQK + d];
        s_qk[tid] = a;
    }
    __syncthreads();
    if (tid < 128) {
        int t = tid & 63;
        int off = (tid < 64) ? 0 : 32;
        float a = 0.f;
        #pragma unroll
        for (int d = 0; d < 32; d++) a += s_qk[off + d]*W1[(off + d)*HIDN + t];
        AB[(b*NN + n)*128 + (tid < 64 ? 0 : 64) + t] = a;
    }
}

// ---------------- fused iteration kernel ---------------------------------------
__global__ __launch_bounds__(256,5) void k_iter(const float* __restrict__ M,
    const float* __restrict__ X, const float* __restrict__ AB,
    const float* __restrict__ T9, const float* __restrict__ gbv,
    const float* __restrict__ b1, const float* __restrict__ W2,
    const float* __restrict__ b2, const float* __restrict__ wo,
    const float* __restrict__ bo,
    const uint4* __restrict__ pBg, const float* __restrict__ bgv,
    const uint4* __restrict__ pBc, const float* __restrict__ bcv,
    const uint4* __restrict__ pBM, const float* __restrict__ bm,
    const float* __restrict__ wq, const float* __restrict__ bq,
    const float* __restrict__ wk, const float* __restrict__ bk,
    const float* __restrict__ W1,
    const int* __restrict__ off, const int* __restrict__ lj,
    float* __restrict__ Xn, float* __restrict__ Mout,
    float* __restrict__ ABout, int doTail)
{
    int bn = blockIdx.x; int b = bn >> 6, i = bn & 63;
    int p16 = (i >> 3)*16, q16 = (i & 7)*16;
    extern __shared__ uint sTu[];               // TILE_BYTES = 25920
    __shared__ float sg[4*144];
    __shared__ float sT9[144];
    __shared__ float sgb[16], s_bg[32], s_bc[16], s_bm[16];
    __shared__ float sb1[64], sb2[64], swo[64];
    __shared__ union {
        struct { float h1s[4][64]; float sred[4][2]; float sev[4]; } head;
        struct { float s_red[16][8]; float s_xm[16]; float s_qk[64]; } tail;
    } u;
    __shared__ int sbase_n[4];

    int tid = threadIdx.x;
    int o0 = off[i], deg = off[i+1] - o0;
    uint sbase = (uint)__cvta_generic_to_shared(sTu);

    // zero agg cp0..7 (incl halo); load X hi-only into cp8..15
    for (int t = tid; t < 324*8; t += 256) {
        int cp = t / 324, pix = t - cp*324;
        sTu[pix*TPITCH_U + cp] = 0u;
    }
    load_tile_hi(sTu, X, 8, b, p16, q16);

    if (tid < 144) sT9[tid] = T9[tid];
    if (tid < 16)  sgb[tid] = gbv[tid];
    if (tid < 32)  s_bg[tid] = bgv[tid];
    if (tid < 16)  s_bc[tid] = bcv[tid];
    if (tid < 16)  s_bm[tid] = bm[tid];
    if (tid < 64)  { sb1[tid] = b1[tid]; sb2[tid] = b2[tid]; swo[tid] = wo[tid]; }
    if (tid < deg) {
        int ej = lj[o0 + tid];
        sbase_n[tid] = ((b*CC)*128 + (ej >> 3)*16)*128 + (ej & 7)*16;
    }
    float bov = bo[0];
    __syncthreads();

    // ---- edge MLP for this node's incident edges (<=4) ----
    int l = tid >> 6, t = tid & 63;
    if (l < deg) {
        int ej = lj[o0 + l];
        float a = AB[(b*NN + i)*128 + t] + AB[(b*NN + ej)*128 + 64 + t] + sb1[t];
        u.head.h1s[l][t] = fmaxf(a, 0.f);
    }
    __syncthreads();
    if (l < deg) {
        float a2 = sb2[t];
        #pragma unroll
        for (int k = 0; k < HIDN; k++) a2 += u.head.h1s[l][k]*__ldg(&W2[k*HIDN + t]);
        a2 = fmaxf(a2, 0.f);
        float part = a2*swo[t];
        #pragma unroll
        for (int o = 16; o; o >>= 1) part += __shfl_down_sync(0xffffffffu, part, o);
        if ((t & 31) == 0) u.head.sred[l][t >> 5] = part;
    }
    __syncthreads();
    if (tid < deg) u.head.sev[tid] = u.head.sred[tid][0] + u.head.sred[tid][1] + bov;
    __syncthreads();

    // ---- gate table ----
    for (int t2 = tid; t2 < deg*144; t2 += 256) {
        int le = t2 / 144, r = t2 - le*144;
        int c = r / 9;
        sg[t2] = sigf(u.head.sev[le]*sT9[r] + sgb[c]);
    }
    __syncthreads();

    // ---- segment-sum of gated messages, hi write into tile ch 0..15 ----
    {
        int cg = tid >> 6, pg = tid & 63;
        int y = pg >> 2, x0 = (pg & 3)*4;
        int cy = (y == 0) ? 0 : ((y == 15) ? 2 : 1);
        int cix[4];
        #pragma unroll
        for (int k = 0; k < 4; k++) {
            int x = x0 + k;
            cix[k] = cy*3 + ((x == 0) ? 0 : ((x == 15) ? 2 : 1));
        }
        int pix = y*128 + x0;
        float av[4][4];
        #pragma unroll
        for (int cc = 0; cc < 4; cc++) {
            int c = cg*4 + cc;
            float a0=0.f,a1=0.f,a2=0.f,a3=0.f;
            for (int le = 0; le < deg; le++) {
                const float* gl = &sg[le*144 + c*9];
                float4 m = *reinterpret_cast<const float4*>(&M[sbase_n[le] + c*PLANE + pix]);
                a0 += gl[cix[0]]*m.x;
                a1 += gl[cix[1]]*m.y;
                a2 += gl[cix[2]]*m.z;
                a3 += gl[cix[3]]*m.w;
            }
            av[cc][0]=a0; av[cc][1]=a1; av[cc][2]=a2; av[cc][3]=a3;
        }
        #pragma unroll
        for (int k = 0; k < 4; k++) {
            int tp = ((y + 1)*18 + (x0 + 1 + k))*TPITCH_U + 2*cg;
            *reinterpret_cast<uint2*>(&sTu[tp]) =
                make_uint2(pkhi(av[0][k], av[1][k]), pkhi(av[2][k], av[3][k]));
        }
    }
    __syncthreads();

    // ---- GRU ----
    int lane = tid & 31, wid = tid >> 5;
    int g = lane >> 2, q = lane & 3, m0 = wid*2;

    uint zpk[2][2][2];   // z gates packed fp16 pairs (8 regs instead of 16)

    {   // gate conv (2-term)
        float acc[2][4][4];
        mma_convh<32,4>(sbase, pBg, s_bg, acc);
        __syncthreads();
        #pragma unroll
        for (int mm = 0; mm < 2; mm++) {
            int y = m0 + mm;
            #pragma unroll
            for (int nt = 0; nt < 4; nt++) {
                int co = nt*8 + q*2;
                if (nt < 2) {
                    #pragma unroll
                    for (int half = 0; half < 2; half++)
                        zpk[mm][nt][half] = pkhi(sigf(acc[mm][nt][half*2]),
                                                 sigf(acc[mm][nt][half*2 + 1]));
                } else {
                    // channels co, co+1 (>=16): r gates -> rh in place
                    #pragma unroll
                    for (int half = 0; half < 2; half++) {
                        int x = g + half*8;
                        int ti = ((y + 1)*18 + (x + 1))*TPITCH_U + co/2;
                        float2 h = hirec(sTu[ti]);
                        float r0 = sigf(acc[mm][nt][half*2]);
                        float r1 = sigf(acc[mm][nt][half*2 + 1]);
                        sTu[ti] = pkhi(r0*h.x, r1*h.y);
                    }
                }
            }
        }
    }
    __syncthreads();

    float cs[2][2];     // per-thread channel sums of Xn (nt, parity) for mean
    cs[0][0] = cs[0][1] = cs[1][0] = cs[1][1] = 0.f;

    {   // candidate conv (2-term) + update (+ tile refill for tail)
        float acc[2][2][4];
        mma_convh<32,2>(sbase, pBc, s_bc, acc);
        __syncthreads();   // all warps' tile reads done before tile overwrite
        #pragma unroll
        for (int mm = 0; mm < 2; mm++) {
            int y = m0 + mm;
            #pragma unroll
            for (int nt = 0; nt < 2; nt++) {
                int co = nt*8 + q*2;
                #pragma unroll
                for (int half = 0; half < 2; half++) {
                    int x = g + half*8;
                    int idx = ((b*CC + co)*128 + p16 + y)*128 + q16 + x;
                    float h0 = X[idx];
                    float h1 = X[idx + PLANE];
                    float cand0 = tanhf(acc[mm][nt][half*2]);
                    float cand1 = tanhf(acc[mm][nt][half*2 + 1]);
                    float2 z = hirec(zpk[mm][nt][half]);
                    float v0 = (1.f - z.x)*h0 + z.x*cand0;
                    float v1 = (1.f - z.y)*h1 + z.y*cand1;
                    Xn[idx]         = v0;
                    Xn[idx + PLANE] = v1;
                    cs[nt][0] += v0;
                    cs[nt][1] += v1;
                    if (doTail) {
                        int pix = (y + 1)*18 + (x + 1);
                        sTu[pix*TPITCH_U + co/2] = pkhi(v0, v1);
                    }
                }
            }
        }
    }

    if (!doTail) return;

    // warp-reduce Xn channel sums over g-lanes (lane bits 2..4), exact fp32
    #pragma unroll
    for (int o = 4; o <= 16; o <<= 1) {
        #pragma unroll
        for (int nt = 0; nt < 2; nt++) {
            cs[nt][0] += __shfl_xor_sync(0xffffffffu, cs[nt][0], o);
            cs[nt][1] += __shfl_xor_sync(0xffffffffu, cs[nt][1], o);
        }
    }
    if (lane < 4) {
        #pragma unroll
        for (int nt = 0; nt < 2; nt++) {
            u.tail.s_red[nt*8 + q*2][wid]     = cs[nt][0];
            u.tail.s_red[nt*8 + q*2 + 1][wid] = cs[nt][1];
        }
    }
    __syncthreads();

    {   // M conv for next iteration (2-term)
        float acc[2][2][4];
        mma_convh<16,2>(sbase, pBM, s_bm, acc);
        #pragma unroll
        for (int mm = 0; mm < 2; mm++) {
            int y = m0 + mm;
            #pragma unroll
            for (int nt = 0; nt < 2; nt++) {
                int co = nt*8 + q*2;
                int r0 = ((b*CC + co)*128 + p16 + y)*128 + q16;
                int r1 = r0 + PLANE;
                Mout[r0 + g]     = acc[mm][nt][0];
                Mout[r1 + g]     = acc[mm][nt][1];
                Mout[r0 + g + 8] = acc[mm][nt][2];
                Mout[r1 + g + 8] = acc[mm][nt][3];
            }
        }
    }
    __syncthreads();
    if (tid < 16) {
        float s = 0.f;
        #pragma unroll
        for (int w = 0; w < 8; w++) s += u.tail.s_red[tid][w];
        u.tail.s_xm[tid] = s * (1.f/256.f);
    }
    __syncthreads();
    if (tid < 64) {
        int d = tid & 31;
        const float* wM = (tid < 32) ? wq : wk;
        const float* bM = (tid < 32) ? bq : bk;
        float a = bM[d];
        #pragma unroll
        for (int c = 0; c < CC; c++) a += u.tail.s_xm[c]*wM[c*DQK + d];
        u.tail.s_qk[tid] = a;
    }
    __syncthreads();
    if (tid < 128) {
        int t2 = tid & 63;
        int offp = (tid < 64) ? 0 : 32;
        float a = 0.f;
        #pragma unroll
        for (int d = 0; d < 32; d++) a += u.tail.s_qk[offp + d]*W1[(offp + d)*HIDN + t2];
        ABout[(b*NN + i)*128 + (tid < 64 ? 0 : 64) + t2] = a;
    }
}

// ---------------- launch ------------------------------------------------------
extern "C" void kernel_launch(void* const* d_in, const int* in_sizes, int n_in,
                              void* d_out, int out_size)
{
    const float* seed = (const float*)d_in[0];
    const int*   eidx = (const int*)  d_in[1];
    const float* wq = (const float*)d_in[2];
    const float* bq = (const float*)d_in[3];
    const float* wk = (const float*)d_in[4];
    const float* bk = (const float*)d_in[5];
    const float* wm = (const float*)d_in[6];
    const float* bm = (const float*)d_in[7];
    const float* w1 = (const float*)d_in[8];
    const float* b1 = (const float*)d_in[9];
    const float* w2 = (const float*)d_in[10];
    const float* b2 = (const float*)d_in[11];
    const float* wo = (const float*)d_in[12];
    const float* bo = (const float*)d_in[13];
    const float* gw = (const float*)d_in[14];
    const float* gb = (const float*)d_in[15];
    const float* wg = (const float*)d_in[16];
    const float* bg = (const float*)d_in[17];
    const float* wc = (const float*)d_in[18];
    const float* bc = (const float*)d_in[19];
    float* out = (float*)d_out;

    int B = in_sizes[0] / (CC*128*128);
    int E = in_sizes[1] / 2;

    void *pXa,*pXb,*pM0,*pM1,*pAB0,*pAB1,*pT9,*poff,*plj,*pBM,*pBg,*pBc;
    cudaGetSymbolAddress(&pXa, g_Xa);   cudaGetSymbolAddress(&pXb, g_Xb);
    cudaGetSymbolAddress(&pM0, g_M0);   cudaGetSymbolAddress(&pM1, g_M1);
    cudaGetSymbolAddress(&pAB0,g_AB0);  cudaGetSymbolAddress(&pAB1,g_AB1);
    cudaGetSymbolAddress(&pT9, g_T9);   cudaGetSymbolAddress(&poff,g_off);
    cudaGetSymbolAddress(&plj, g_lj);
    cudaGetSymbolAddress(&pBM, g_pBM);  cudaGetSymbolAddress(&pBg, g_pBg);
    cudaGetSymbolAddress(&pBc, g_pBc);

    cudaFuncSetAttribute(k_iter, cudaFuncAttributeMaxDynamicSharedMemorySize,
                         TILE_BYTES);
    cudaFuncSetAttribute(k_convQ, cudaFuncAttributeMaxDynamicSharedMemorySize,
                         TILE_BYTES);

    // launch order fixed so ncu (-s 5 -c 1) captures a full k_iter (6th launch)
    k_csrT9 <<<1, 256>>>(eidx, E, (int*)poff, (int*)plj, gw, (float*)pT9);
    k_prepAll<<<16, 256>>>(wm, wg, wc, (uint4*)pBM, (uint4*)pBg, (uint4*)pBc);
    k_convQ<<<B*NN, 256, TILE_BYTES>>>(seed, (const uint4*)pBM, bm,
                           wq, bq, wk, bk, w1, (float*)pM0, (float*)pAB0);

    const float* Xc = seed;
    for (int it = 0; it < 4; it++) {
        float* Xn = (it == 3) ? out : ((it & 1) ? (float*)pXb : (float*)pXa);
        float* Mi  = (it & 1) ? (float*)pM1  : (float*)pM0;
        float* Mo  = (it & 1) ? (float*)pM0  : (float*)pM1;
        float* ABi = (it & 1) ? (float*)pAB1 : (float*)pAB0;
        float* ABo = (it & 1) ? (float*)pAB0 : (float*)pAB1;

        k_iter<<<B*NN, 256, TILE_BYTES>>>(Mi, Xc, ABi,
                        (const float*)pT9, gb, b1, w2, b2, wo, bo,
                        (const uint4*)pBg, bg,
                        (const uint4*)pBc, bc,
                        (const uint4*)pBM, bm,
                        wq, bq, wk, bk, w1,
                        (const int*)poff, (const int*)plj,
                        Xn, Mo, ABo, (it < 3) ? 1 : 0);
        Xc = Xn;
    }
}

// round 17
// speedup vs baseline: 2.2670x; 2.2670x over previous
#include <cuda_runtime.h>
#include <cuda_fp16.h>

typedef unsigned int uint;

// Problem constants (fixed by the dataset)
#define CC     16
#define NN     64
#define DQK    32
#define HIDN   64
#define MAXE   512
#define BMAX   16
#define PLANE  16384

// pixel-major fp16 tile (hi only): [324 pixels][20 uints pitch], 16 ch-pairs
#define TPITCH_U 20
#define TILE_U   (324*TPITCH_U)
#define TILE_BYTES (TILE_U*4)            // 25920

// ---------------- scratch ----------------------------------------------------
__device__ float g_Xa [BMAX*CC*PLANE];
__device__ float g_Xb [BMAX*CC*PLANE];
__device__ float g_M0 [BMAX*CC*PLANE];
__device__ float g_M1 [BMAX*CC*PLANE];
__device__ float g_AB0[BMAX*NN*128];
__device__ float g_AB1[BMAX*NN*128];
__device__ float g_T9 [CC*9];
__device__ int   g_off[NN+1];
__device__ int   g_lj [MAXE];
// fp16-split weight fragment tables: [(ks*N + n)*4 + q] -> (b0h,b1h,b0l,b1l)
__device__ uint4 g_pBM[9*16*4];
__device__ uint4 g_pBg[18*32*4];
__device__ uint4 g_pBc[18*16*4];

__device__ __forceinline__ float sigf(float x){ return 1.f/(1.f+__expf(-x)); }

// ---------------- fp16 helpers ------------------------------------------------
__device__ __forceinline__ uint packh2(__half a, __half b){
    __half2 h = __halves2half2(a, b);
    return *reinterpret_cast<uint*>(&h);
}
__device__ __forceinline__ uint pkhi(float v0, float v1){
    __half2 h = __floats2half2_rn(v0, v1);
    return *reinterpret_cast<uint*>(&h);
}
__device__ __forceinline__ float2 hirec(uint e){
    __half2 hh = *reinterpret_cast<__half2*>(&e);
    return __half22float2(hh);
}

__device__ __forceinline__ void mmah(float c[4], const uint a[4], uint b0, uint b1){
    asm volatile("mma.sync.aligned.m16n8k16.row.col.f32.f16.f16.f32 "
        "{%0,%1,%2,%3},{%4,%5,%6,%7},{%8,%9},{%0,%1,%2,%3};"
        : "+f"(c[0]),"+f"(c[1]),"+f"(c[2]),"+f"(c[3])
        : "r"(a[0]),"r"(a[1]),"r"(a[2]),"r"(a[3]),"r"(b0),"r"(b1));
}

__device__ __forceinline__ void ldsm4(uint r[4], uint addr){
    asm volatile("ldmatrix.sync.aligned.m8n8.x4.shared.b16 {%0,%1,%2,%3}, [%4];"
        : "=r"(r[0]),"=r"(r[1]),"=r"(r[2]),"=r"(r[3]) : "r"(addr));
}

// ---------------- weight prepack (runs once) ----------------------------------
__device__ __forceinline__ void prep_one(const float* __restrict__ W,
                                         uint4* __restrict__ out,
                                         int CIN, int N, int i)
{
    int q = i & 3; int t = i >> 2; int n = t % N; int ks = t / N;
    float w[4]; __half h[4], l[4];
    int kk[4] = { ks*16 + 2*q, ks*16 + 2*q + 1, ks*16 + 2*q + 8, ks*16 + 2*q + 9 };
    #pragma unroll
    for (int j = 0; j < 4; j++) {
        int k = kk[j];
        w[j] = W[n*CIN*9 + (k % CIN)*9 + (k / CIN)];
        h[j] = __float2half_rn(w[j]);
        l[j] = __float2half_rn(w[j] - __half2float(h[j]));
    }
    uint4 o;
    o.x = packh2(h[0], h[1]);
    o.y = packh2(h[2], h[3]);
    o.z = packh2(l[0], l[1]);
    o.w = packh2(l[2], l[3]);
    out[(ks*N + n)*4 + q] = o;
}

__global__ void k_prepAll(const float* __restrict__ wm,
                          const float* __restrict__ wg,
                          const float* __restrict__ wc,
                          uint4* __restrict__ outM, uint4* __restrict__ outG,
                          uint4* __restrict__ outC)
{
    int i = blockIdx.x*256 + threadIdx.x;
    if (i < 576)       prep_one(wm, outM, 16, 16, i);
    else if (i < 2880) prep_one(wg, outG, 32, 32, i - 576);
    else if (i < 4032) prep_one(wc, outC, 32, 16, i - 2880);
}

// csr build + T9 table in one launch
__global__ void k_csrT9(const int* __restrict__ eidx, int E,
                        int* __restrict__ off, int* __restrict__ lj,
                        const float* __restrict__ gw, float* __restrict__ T9)
{
    __shared__ int se[MAXE*2];
    int tid = threadIdx.x;
    for (int i = tid; i < 2*E; i += 256) se[i] = eidx[i];
    if (tid < CC*9) {
        int c = tid / 9, cls = tid - c*9, ry = cls/3, rx = cls - ry*3;
        float s = 0.f;
        #pragma unroll
        for (int ky = 0; ky < 3; ky++) {
            if ((ry == 0 && ky == 0) || (ry == 2 && ky == 2)) continue;
            #pragma unroll
            for (int kx = 0; kx < 3; kx++) {
                if ((rx == 0 && kx == 0) || (rx == 2 && kx == 2)) continue;
                s += gw[c*9 + ky*3 + kx];
            }
        }
        T9[tid] = s;
    }
    __syncthreads();
    if (tid == 0) {
        int cnt[NN];
        for (int i = 0; i < NN; i++) cnt[i] = 0;
        for (int e = 0; e < E; e++) cnt[se[2*e]]++;
        int acc = 0;
        for (int i = 0; i < NN; i++) { off[i] = acc; acc += cnt[i]; cnt[i] = 0; }
        off[NN] = acc;
        for (int e = 0; e < E; e++) {
            int i = se[2*e];
            int s = off[i] + cnt[i]++;
            lj[s] = se[2*e + 1];
        }
    }
}

// ---------------- tile loader (pixel-major, hi only) ---------------------------
__device__ __forceinline__ void load_tile_hi(uint* sTu,
        const float* __restrict__ src, int cp0,
        int b, int p16, int q16)
{
    for (int i = threadIdx.x; i < 324*8; i += 256) {
        int cp = i / 324; int pix = i - cp*324;
        int yy = pix/18, xx = pix - yy*18;
        int ly = yy - 1, lx = xx - 1;
        float v0 = 0.f, v1 = 0.f;
        if ((unsigned)ly < 16u && (unsigned)lx < 16u) {
            const float* p = &src[((b*CC + 2*cp)*128 + p16 + ly)*128 + (q16 + lx)];
            v0 = p[0]; v1 = p[PLANE];
        }
        sTu[pix*TPITCH_U + cp0 + cp] = pkhi(v0, v1);
    }
}

// ---------------- fp16 2-term conv GEMM core (ldmatrix, sw-pipelined) ----------
template<int CIN,int NT>
__device__ __forceinline__ void mma_convh(uint sbase,
                                          const uint4* __restrict__ pB,
                                          const float* s_bias,
                                          float acc[2][NT][4])
{
    constexpr int N = NT*8;
    constexpr int KSTEPS = CIN*9/16;
    int lane = threadIdx.x & 31;
    int wid  = threadIdx.x >> 5;
    int g = lane >> 2, q = lane & 3;
    int m0 = wid*2;
    int x = lane & 15, colsel = lane >> 4;

    #pragma unroll
    for (int mm = 0; mm < 2; mm++)
        #pragma unroll
        for (int nt = 0; nt < NT; nt++) {
            float b0 = s_bias[nt*8 + q*2], b1 = s_bias[nt*8 + q*2 + 1];
            acc[mm][nt][0] = b0; acc[mm][nt][1] = b1;
            acc[mm][nt][2] = b0; acc[mm][nt][3] = b1;
        }

    #pragma unroll 2
    for (int ks = 0; ks < KSTEPS; ks++) {
        int tap = (CIN == 16) ? ks : (ks >> 1);
        int sub = (CIN == 16) ? 0  : (ks & 1);
        int ty = tap/3, tx = tap - ty*3;
        uint ah[2][4];
        uint4 bv[NT];
        #pragma unroll
        for (int mm = 0; mm < 2; mm++) {
            int row = (m0 + mm + ty)*18 + x + tx;
            uint addr = sbase + (uint)((row*40 + sub*16 + colsel*8)*2);
            ldsm4(ah[mm], addr);
        }
        #pragma unroll
        for (int nt = 0; nt < NT; nt++)
            bv[nt] = pB[(ks*N + nt*8 + g)*4 + q];
        #pragma unroll
        for (int nt = 0; nt < NT; nt++) {
            #pragma unroll
            for (int mm = 0; mm < 2; mm++) {
                mmah(acc[mm][nt], ah[mm], bv[nt].x, bv[nt].y);
                mmah(acc[mm][nt], ah[mm], bv[nt].z, bv[nt].w);
            }
        }
    }
}

// ---------------- initial conv + mean/qk/AB kernel (seed only) ----------------
__global__ __launch_bounds__(256) void k_convQ(const float* __restrict__ X,
    const uint4* __restrict__ pBM, const float* __restrict__ bm,
    const float* __restrict__ wq, const float* __restrict__ bq,
    const float* __restrict__ wk, const float* __restrict__ bk,
    const float* __restrict__ W1,
    float* __restrict__ M, float* __restrict__ AB)
{
    int bn = blockIdx.x; int b = bn >> 6, n = bn & 63;
    int p16 = (n >> 3)*16, q16 = (n & 7)*16;
    extern __shared__ uint sTu[];
    __shared__ float s_bias[16];
    __shared__ float s_xm[16];
    __shared__ float s_qk[64];
    load_tile_hi(sTu, X, 0, b, p16, q16);
    if (threadIdx.x < 16) s_bias[threadIdx.x] = bm[threadIdx.x];

    int tid = threadIdx.x;
    uint sbase = (uint)__cvta_generic_to_shared(sTu);
    {
        int w = tid >> 5, lane = tid & 31;
        for (int c = w*2; c < w*2 + 2; c++) {
            float s = 0.f;
            for (int i = lane; i < 256; i += 32) {
                int y = i >> 4, x = i & 15;
                s += X[((b*CC + c)*128 + p16 + y)*128 + q16 + x];
            }
            #pragma unroll
            for (int o = 16; o; o >>= 1) s += __shfl_down_sync(0xffffffffu, s, o);
            if (!lane) s_xm[c] = s * (1.f/256.f);
        }
    }
    __syncthreads();

    float acc[2][2][4];
    mma_convh<16,2>(sbase, pBM, s_bias, acc);

    int lane = tid & 31, wid = tid >> 5;
    int g = lane >> 2, q = lane & 3, m0 = wid*2;
    #pragma unroll
    for (int mm = 0; mm < 2; mm++) {
        int y = m0 + mm;
        #pragma unroll
        for (int nt = 0; nt < 2; nt++) {
            int co = nt*8 + q*2;
            int r0 = ((b*CC + co)*128 + p16 + y)*128 + q16;
            int r1 = r0 + PLANE;
            M[r0 + g]     = acc[mm][nt][0];
            M[r1 + g]     = acc[mm][nt][1];
            M[r0 + g + 8] = acc[mm][nt][2];
            M[r1 + g + 8] = acc[mm][nt][3];
        }
    }
    __syncthreads();
    if (tid < 64) {
        int d = tid & 31;
        const float* wM = (tid < 32) ? wq : wk;
        const float* bM = (tid < 32) ? bq : bk;
        float a = bM[d];
        #pragma unroll
        for (int c = 0; c < CC; c++) a += s_xm[c]*wM[c*DQK + d];
        s_qk[tid] = a;
    }
    __syncthreads();
    if (tid < 128) {
        int t = tid & 63;
        int off = (tid < 64) ? 0 : 32;
        float a = 0.f;
        #pragma unroll
        for (int d = 0; d < 32; d++) a += s_qk[off + d]*W1[(off + d)*HIDN + t];
        AB[(b*NN + n)*128 + (tid < 64 ? 0 : 64) + t] = a;
    }
}

// ---------------- fused iteration kernel ---------------------------------------
__global__ __launch_bounds__(256,4) void k_iter(const float* __restrict__ M,
    const float* __restrict__ X, const float* __restrict__ AB,
    const float* __restrict__ T9, const float* __restrict__ gbv,
    const float* __restrict__ b1, const float* __restrict__ W2,
    const float* __restrict__ b2, const float* __restrict__ wo,
    const float* __restrict__ bo,
    const uint4* __restrict__ pBg, const float* __restrict__ bgv,
    const uint4* __restrict__ pBc, const float* __restrict__ bcv,
    const uint4* __restrict__ pBM, const float* __restrict__ bm,
    const float* __restrict__ wq, const float* __restrict__ bq,
    const float* __restrict__ wk, const float* __restrict__ bk,
    const float* __restrict__ W1,
    const int* __restrict__ off, const int* __restrict__ lj,
    float* __restrict__ Xn, float* __restrict__ Mout,
    float* __restrict__ ABout, int doTail)
{
    int bn = blockIdx.x; int b = bn >> 6, i = bn & 63;
    int p16 = (i >> 3)*16, q16 = (i & 7)*16;
    extern __shared__ uint sTu[];               // TILE_BYTES = 25920
    __shared__ float sg[4*144];
    __shared__ float sT9[144];
    __shared__ float sgb[16], s_bg[32], s_bc[16], s_bm[16];
    __shared__ float sb1[64], sb2[64], swo[64];
    __shared__ union {
        struct { float h1s[4][64]; float sred[4][2]; float sev[4]; } head;
        struct { float s_red[16][8]; float s_xm[16]; float s_qk[64]; } tail;
    } u;
    __shared__ int sbase_n[4];

    int tid = threadIdx.x;
    int o0 = off[i], deg = off[i+1] - o0;
    uint sbase = (uint)__cvta_generic_to_shared(sTu);

    // zero agg cp0..7 (incl halo); load X hi-only into cp8..15
    for (int t = tid; t < 324*8; t += 256) {
        int cp = t / 324, pix = t - cp*324;
        sTu[pix*TPITCH_U + cp] = 0u;
    }
    load_tile_hi(sTu, X, 8, b, p16, q16);

    if (tid < 144) sT9[tid] = T9[tid];
    if (tid < 16)  sgb[tid] = gbv[tid];
    if (tid < 32)  s_bg[tid] = bgv[tid];
    if (tid < 16)  s_bc[tid] = bcv[tid];
    if (tid < 16)  s_bm[tid] = bm[tid];
    if (tid < 64)  { sb1[tid] = b1[tid]; sb2[tid] = b2[tid]; swo[tid] = wo[tid]; }
    if (tid < deg) {
        int ej = lj[o0 + tid];
        sbase_n[tid] = ((b*CC)*128 + (ej >> 3)*16)*128 + (ej & 7)*16;
    }
    float bov = bo[0];
    __syncthreads();

    // ---- edge MLP for this node's incident edges (<=4) ----
    int l = tid >> 6, t = tid & 63;
    if (l < deg) {
        int ej = lj[o0 + l];
        float a = AB[(b*NN + i)*128 + t] + AB[(b*NN + ej)*128 + 64 + t] + sb1[t];
        u.head.h1s[l][t] = fmaxf(a, 0.f);
    }
    __syncthreads();
    if (l < deg) {
        float a2 = sb2[t];
        #pragma unroll
        for (int k = 0; k < HIDN; k++) a2 += u.head.h1s[l][k]*__ldg(&W2[k*HIDN + t]);
        a2 = fmaxf(a2, 0.f);
        float part = a2*swo[t];
        #pragma unroll
        for (int o = 16; o; o >>= 1) part += __shfl_down_sync(0xffffffffu, part, o);
        if ((t & 31) == 0) u.head.sred[l][t >> 5] = part;
    }
    __syncthreads();
    if (tid < deg) u.head.sev[tid] = u.head.sred[tid][0] + u.head.sred[tid][1] + bov;
    __syncthreads();

    // ---- gate table ----
    for (int t2 = tid; t2 < deg*144; t2 += 256) {
        int le = t2 / 144, r = t2 - le*144;
        int c = r / 9;
        sg[t2] = sigf(u.head.sev[le]*sT9[r] + sgb[c]);
    }
    __syncthreads();

    // ---- segment-sum of gated messages, hi write into tile ch 0..15 ----
    {
        int cg = tid >> 6, pg = tid & 63;
        int y = pg >> 2, x0 = (pg & 3)*4;
        int cy = (y == 0) ? 0 : ((y == 15) ? 2 : 1);
        int cix[4];
        #pragma unroll
        for (int k = 0; k < 4; k++) {
            int x = x0 + k;
            cix[k] = cy*3 + ((x == 0) ? 0 : ((x == 15) ? 2 : 1));
        }
        int pix = y*128 + x0;
        float av[4][4];
        #pragma unroll
        for (int cc = 0; cc < 4; cc++) {
            int c = cg*4 + cc;
            float a0=0.f,a1=0.f,a2=0.f,a3=0.f;
            for (int le = 0; le < deg; le++) {
                const float* gl = &sg[le*144 + c*9];
                float4 m = *reinterpret_cast<const float4*>(&M[sbase_n[le] + c*PLANE + pix]);
                a0 += gl[cix[0]]*m.x;
                a1 += gl[cix[1]]*m.y;
                a2 += gl[cix[2]]*m.z;
                a3 += gl[cix[3]]*m.w;
            }
            av[cc][0]=a0; av[cc][1]=a1; av[cc][2]=a2; av[cc][3]=a3;
        }
        #pragma unroll
        for (int k = 0; k < 4; k++) {
            int tp = ((y + 1)*18 + (x0 + 1 + k))*TPITCH_U + 2*cg;
            *reinterpret_cast<uint2*>(&sTu[tp]) =
                make_uint2(pkhi(av[0][k], av[1][k]), pkhi(av[2][k], av[3][k]));
        }
    }
    __syncthreads();

    // ---- GRU ----
    int lane = tid & 31, wid = tid >> 5;
    int g = lane >> 2, q = lane & 3, m0 = wid*2;

    uint zpk[2][2][2];   // z gates packed fp16 pairs

    {   // gate conv (2-term)
        float acc[2][4][4];
        mma_convh<32,4>(sbase, pBg, s_bg, acc);
        __syncthreads();
        #pragma unroll
        for (int mm = 0; mm < 2; mm++) {
            int y = m0 + mm;
            #pragma unroll
            for (int nt = 0; nt < 4; nt++) {
                int co = nt*8 + q*2;
                if (nt < 2) {
                    #pragma unroll
                    for (int half = 0; half < 2; half++)
                        zpk[mm][nt][half] = pkhi(sigf(acc[mm][nt][half*2]),
                                                 sigf(acc[mm][nt][half*2 + 1]));
                } else {
                    // channels co, co+1 (>=16): r gates -> rh in place
                    #pragma unroll
                    for (int half = 0; half < 2; half++) {
                        int x = g + half*8;
                        int ti = ((y + 1)*18 + (x + 1))*TPITCH_U + co/2;
                        float2 h = hirec(sTu[ti]);
                        float r0 = sigf(acc[mm][nt][half*2]);
                        float r1 = sigf(acc[mm][nt][half*2 + 1]);
                        sTu[ti] = pkhi(r0*h.x, r1*h.y);
                    }
                }
            }
        }
    }
    __syncthreads();

    float cs[2][2];     // per-thread channel sums of Xn (nt, parity) for mean
    cs[0][0] = cs[0][1] = cs[1][0] = cs[1][1] = 0.f;

    {   // candidate conv (2-term) + update (+ tile refill for tail)
        float acc[2][2][4];
        mma_convh<32,2>(sbase, pBc, s_bc, acc);
        __syncthreads();   // all warps' tile reads done before tile overwrite
        #pragma unroll
        for (int mm = 0; mm < 2; mm++) {
            int y = m0 + mm;
            #pragma unroll
            for (int nt = 0; nt < 2; nt++) {
                int co = nt*8 + q*2;
                #pragma unroll
                for (int half = 0; half < 2; half++) {
                    int x = g + half*8;
                    int idx = ((b*CC + co)*128 + p16 + y)*128 + q16 + x;
                    float h0 = X[idx];
                    float h1 = X[idx + PLANE];
                    float cand0 = tanhf(acc[mm][nt][half*2]);
                    float cand1 = tanhf(acc[mm][nt][half*2 + 1]);
                    float2 z = hirec(zpk[mm][nt][half]);
                    float v0 = (1.f - z.x)*h0 + z.x*cand0;
                    float v1 = (1.f - z.y)*h1 + z.y*cand1;
                    Xn[idx]         = v0;
                    Xn[idx + PLANE] = v1;
                    cs[nt][0] += v0;
                    cs[nt][1] += v1;
                    if (doTail) {
                        int pix = (y + 1)*18 + (x + 1);
                        sTu[pix*TPITCH_U + co/2] = pkhi(v0, v1);
                    }
                }
            }
        }
    }

    if (!doTail) return;

    // warp-reduce Xn channel sums over g-lanes (lane bits 2..4), exact fp32
    #pragma unroll
    for (int o = 4; o <= 16; o <<= 1) {
        #pragma unroll
        for (int nt = 0; nt < 2; nt++) {
            cs[nt][0] += __shfl_xor_sync(0xffffffffu, cs[nt][0], o);
            cs[nt][1] += __shfl_xor_sync(0xffffffffu, cs[nt][1], o);
        }
    }
    if (lane < 4) {
        #pragma unroll
        for (int nt = 0; nt < 2; nt++) {
            u.tail.s_red[nt*8 + q*2][wid]     = cs[nt][0];
            u.tail.s_red[nt*8 + q*2 + 1][wid] = cs[nt][1];
        }
    }
    __syncthreads();

    {   // M conv for next iteration (2-term)
        float acc[2][2][4];
        mma_convh<16,2>(sbase, pBM, s_bm, acc);
        #pragma unroll
        for (int mm = 0; mm < 2; mm++) {
            int y = m0 + mm;
            #pragma unroll
            for (int nt = 0; nt < 2; nt++) {
                int co = nt*8 + q*2;
                int r0 = ((b*CC + co)*128 + p16 + y)*128 + q16;
                int r1 = r0 + PLANE;
                Mout[r0 + g]     = acc[mm][nt][0];
                Mout[r1 + g]     = acc[mm][nt][1];
                Mout[r0 + g + 8] = acc[mm][nt][2];
                Mout[r1 + g + 8] = acc[mm][nt][3];
            }
        }
    }
    __syncthreads();
    if (tid < 16) {
        float s = 0.f;
        #pragma unroll
        for (int w = 0; w < 8; w++) s += u.tail.s_red[tid][w];
        u.tail.s_xm[tid] = s * (1.f/256.f);
    }
    __syncthreads();
    if (tid < 64) {
        int d = tid & 31;
        const float* wM = (tid < 32) ? wq : wk;
        const float* bM = (tid < 32) ? bq : bk;
        float a = bM[d];
        #pragma unroll
        for (int c = 0; c < CC; c++) a += u.tail.s_xm[c]*wM[c*DQK + d];
        u.tail.s_qk[tid] = a;
    }
    __syncthreads();
    if (tid < 128) {
        int t2 = tid & 63;
        int offp = (tid < 64) ? 0 : 32;
        float a = 0.f;
        #pragma unroll
        for (int d = 0; d < 32; d++) a += u.tail.s_qk[offp + d]*W1[(offp + d)*HIDN + t2];
        ABout[(b*NN + i)*128 + (tid < 64 ? 0 : 64) + t2] = a;
    }
}

// ---------------- launch ------------------------------------------------------
extern "C" void kernel_launch(void* const* d_in, const int* in_sizes, int n_in,
                              void* d_out, int out_size)
{
    const float* seed = (const float*)d_in[0];
    const int*   eidx = (const int*)  d_in[1];
    const float* wq = (const float*)d_in[2];
    const float* bq = (const float*)d_in[3];
    const float* wk = (const float*)d_in[4];
    const float* bk = (const float*)d_in[5];
    const float* wm = (const float*)d_in[6];
    const float* bm = (const float*)d_in[7];
    const float* w1 = (const float*)d_in[8];
    const float* b1 = (const float*)d_in[9];
    const float* w2 = (const float*)d_in[10];
    const float* b2 = (const float*)d_in[11];
    const float* wo = (const float*)d_in[12];
    const float* bo = (const float*)d_in[13];
    const float* gw = (const float*)d_in[14];
    const float* gb = (const float*)d_in[15];
    const float* wg = (const float*)d_in[16];
    const float* bg = (const float*)d_in[17];
    const float* wc = (const float*)d_in[18];
    const float* bc = (const float*)d_in[19];
    float* out = (float*)d_out;

    int B = in_sizes[0] / (CC*128*128);
    int E = in_sizes[1] / 2;

    void *pXa,*pXb,*pM0,*pM1,*pAB0,*pAB1,*pT9,*poff,*plj,*pBM,*pBg,*pBc;
    cudaGetSymbolAddress(&pXa, g_Xa);   cudaGetSymbolAddress(&pXb, g_Xb);
    cudaGetSymbolAddress(&pM0, g_M0);   cudaGetSymbolAddress(&pM1, g_M1);
    cudaGetSymbolAddress(&pAB0,g_AB0);  cudaGetSymbolAddress(&pAB1,g_AB1);
    cudaGetSymbolAddress(&pT9, g_T9);   cudaGetSymbolAddress(&poff,g_off);
    cudaGetSymbolAddress(&plj, g_lj);
    cudaGetSymbolAddress(&pBM, g_pBM);  cudaGetSymbolAddress(&pBg, g_pBg);
    cudaGetSymbolAddress(&pBc, g_pBc);

    cudaFuncSetAttribute(k_iter, cudaFuncAttributeMaxDynamicSharedMemorySize,
                         TILE_BYTES);
    cudaFuncSetAttribute(k_convQ, cudaFuncAttributeMaxDynamicSharedMemorySize,
                         TILE_BYTES);

    // launch order fixed so ncu (-s 5 -c 1) captures a full k_iter (6th launch)
    k_csrT9 <<<1, 256>>>(eidx, E, (int*)poff, (int*)plj, gw, (float*)pT9);
    k_prepAll<<<16, 256>>>(wm, wg, wc, (uint4*)pBM, (uint4*)pBg, (uint4*)pBc);
    k_convQ<<<B*NN, 256, TILE_BYTES>>>(seed, (const uint4*)pBM, bm,
                           wq, bq, wk, bk, w1, (float*)pM0, (float*)pAB0);

    const float* Xc = seed;
    for (int it = 0; it < 4; it++) {
        float* Xn = (it == 3) ? out : ((it & 1) ? (float*)pXb : (float*)pXa);
        float* Mi  = (it & 1) ? (float*)pM1  : (float*)pM0;
        float* Mo  = (it & 1) ? (float*)pM0  : (float*)pM1;
        float* ABi = (it & 1) ? (float*)pAB1 : (float*)pAB0;
        float* ABo = (it & 1) ? (float*)pAB0 : (float*)pAB1;

        k_iter<<<B*NN, 256, TILE_BYTES>>>(Mi, Xc, ABi,
                        (const float*)pT9, gb, b1, w2, b2, wo, bo,
                        (const uint4*)pBg, bg,
                        (const uint4*)pBc, bc,
                        (const uint4*)pBM, bm,
                        wq, bq, wk, bk, w1,
                        (const int*)poff, (const int*)plj,
                        Xn, Mo, ABo, (it < 3) ? 1 : 0);
        Xc = Xn;
    }
}